// round 3
// baseline (speedup 1.0000x reference)
#include <cuda_runtime.h>
#include <math.h>

#define NX 64
#define NUN 256
#define NY 32
#define NZ 384        // 2*NX + NUN
#define BATCH 32768
#define NSTATE 384    // 128 (z = x||u) + 256 (w)
#define EPB 128       // batch elements per block
#define PAIRS 64      // f32x2 pairs per block
#define TB 256        // threads per block (8 warps)
#define SSTRIDE 65    // padded state row stride in ULL (conflict-free)

typedef unsigned long long ULL;

// ---------------- f32x2 helpers (ptxas only emits FFMA2 from PTX) -------
__device__ __forceinline__ ULL ffma2(ULL a, ULL b, ULL c) {
    ULL d; asm("fma.rn.f32x2 %0, %1, %2, %3;" : "=l"(d) : "l"(a), "l"(b), "l"(c)); return d;
}
__device__ __forceinline__ ULL fadd2(ULL a, ULL b) {
    ULL d; asm("add.rn.f32x2 %0, %1, %2;" : "=l"(d) : "l"(a), "l"(b)); return d;
}
__device__ __forceinline__ ULL pack2(float lo, float hi) {
    ULL d; asm("mov.b64 %0, {%1,%2};" : "=l"(d) : "f"(lo), "f"(hi)); return d;
}
__device__ __forceinline__ void unpack2(ULL v, float& lo, float& hi) {
    asm("mov.b64 {%0,%1}, %2;" : "=f"(lo), "=f"(hi) : "l"(v));
}
__device__ __forceinline__ ULL shfl_xor64(ULL v, int m) {
    return __shfl_xor_sync(0xFFFFFFFFu, v, m, 32);
}

// ---------------- device scratch (no cudaMalloc allowed) ----------------
__device__ __align__(16) float g_lT1[NZ * 64];
__device__ __align__(16) float g_lT2[NZ * 32];
__device__ __align__(16) float g_M1[NZ * 64];
__device__ __align__(16) float g_M2[NZ * 32];
__device__ __align__(16) float g_H[256 * 320];     // H[64+r][c], c in [0,320)
__device__ __align__(16) float g_MT[256 * NSTATE]; // row i: [C1*il | D12*il | Drows*il]
__device__ __align__(16) float g_bias[256];        // b_w[i] / lam[i]
__device__ __align__(16) float g_D21T[256 * 32];   // [unit][y]

// ---------------- setup kernels (batch-independent weights) --------------

__global__ void k_build_lT(const float* __restrict__ B2, const float* __restrict__ C2,
                           const float* __restrict__ D12, const float* __restrict__ D21,
                           const float* __restrict__ St) {
    int r = blockIdx.x;      // 0..383
    int k = threadIdx.x;     // 0..63
    float v1;
    if (r < 64) {
        float s = 0.f;
        for (int m = 0; m < 32; m++) s += St[k * 32 + m] * C2[m * 64 + r];
        v1 = s;
    } else if (r < 320) {
        int rr = r - 64;
        float s = 0.f;
        for (int m = 0; m < 32; m++) s += St[k * 32 + m] * D21[m * 256 + rr];
        v1 = s - D12[rr * 64 + k];
    } else {
        v1 = B2[(r - 320) * 64 + k];
    }
    g_lT1[r * 64 + k] = v1;
    if (k < 32) {
        float v2;
        if (r < 64)        v2 = C2[k * 64 + r];
        else if (r < 320)  v2 = D21[k * 256 + (r - 64)];
        else               v2 = 0.f;
        g_lT2[r * 32 + k] = v2;
    }
}

__global__ void k_build_M(const float* __restrict__ Rinv, const float* __restrict__ Q) {
    int r = blockIdx.x, k = threadIdx.x;
    float s = 0.f;
    for (int t = 0; t < 64; t++) s += g_lT1[r * 64 + t] * Rinv[t * 64 + k];
    g_M1[r * 64 + k] = s;
    if (k < 32) {
        float s2 = 0.f;
        for (int t = 0; t < 32; t++) s2 += g_lT2[r * 32 + t] * Q[t * 32 + k];
        g_M2[r * 32 + k] = s2;
    }
}

__global__ void k_build_H(const float* __restrict__ X) {
    int idx = blockIdx.x * blockDim.x + threadIdx.x;
    if (idx >= 256 * 320) return;
    int r = idx / 320, c = idx % 320;
    int a = 64 + r;
    float h = 0.f;
    for (int t = 0; t < NZ; t++) h += X[t * NZ + a] * X[t * NZ + c];
    if (c == a) h += 0.001f;
    float h1 = 0.f;
    for (int k = 0; k < 64; k++) h1 += g_M1[a * 64 + k] * g_lT1[c * 64 + k];
    float h2 = 0.f;
    for (int k = 0; k < 32; k++) h2 += g_M2[a * 32 + k] * g_lT2[c * 32 + k];
    g_H[idx] = h + h1 - h2;
}

// fused: lam/bias + MT row + D21T row
__global__ void k_finalize(const float* __restrict__ D12, const float* __restrict__ D21,
                           const float* __restrict__ b) {
    int i = blockIdx.x; // 0..255
    __shared__ float s_inv;
    if (threadIdx.x == 0) {
        float lam = 0.5f * g_H[i * 320 + 64 + i];
        float inv = 1.f / lam;
        s_inv = inv;
        g_bias[i] = b[64 + i] * inv;
    }
    __syncthreads();
    float inv = s_inv;
    for (int t = threadIdx.x; t < NSTATE; t += blockDim.x) {
        float val;
        if (t < 64) {
            val = -g_H[i * 320 + t] * inv;                 // C_1[i][t] / lam
        } else if (t < 128) {
            val = D12[i * 64 + (t - 64)] * inv;            // D_12 / lam
        } else {
            int j = t - 128;
            val = (i >= 1 && j <= i - 2) ? (-g_H[(i - 1) * 320 + 64 + j]) * inv : 0.f;
        }
        g_MT[i * NSTATE + t] = val;
    }
    if (threadIdx.x < 32) g_D21T[i * 32 + threadIdx.x] = D21[threadIdx.x * 256 + i];
}

// ---------------- main kernel ---------------------------------------------
// 128 elems/block as 64 f32x2 pairs. 256 threads = 8 warps.
// Warp w owns pairs 8w..8w+7. Lane = (q<<3)|pair_local, q in 0..3:
//   all lanes : partial GEMM over p-blocks p = 4t+q (quarter-split)
//   shfl_xor reduction (intra-warp) -> q==0 lanes do serial diag + tanh
//   y-GEMM distributed: quarter q owns outputs m = 8q..8q+7 (no reduction)
//
// Shared (ULL units):
//   s_state [384][65]          24960
//   s_coef  [8][384] (dup)      3072   (reused as y-output staging)
//   s_d21   [8][32]  (dup)       256
//   s_bias  [8]                    8
//   s_c2    [4][32]  (dup)       128
//   total 28424 ULL = 227392 B

#define SM_COEF  (NSTATE * SSTRIDE)          // 24960
#define SM_D21   (SM_COEF + 8 * NSTATE)      // 28032
#define SM_BIAS  (SM_D21 + 256)              // 28288
#define SM_C2    (SM_BIAS + 8)               // 28296
#define SM_TOTAL (SM_C2 + 128)               // 28424 ULLs

__global__ void __launch_bounds__(TB, 1)
k_main(const float* __restrict__ u, const float* __restrict__ x0,
       const float* __restrict__ C2, const float* __restrict__ b,
       float* __restrict__ out) {
    extern __shared__ ULL sh[];
    ULL* s_state = sh;
    ULL* s_coef  = sh + SM_COEF;
    ULL* s_d21   = sh + SM_D21;
    ULL* s_bias  = sh + SM_BIAS;
    ULL* s_c2    = sh + SM_C2;

    const int tid  = threadIdx.x;
    const int lane = tid & 31;
    const int warp = tid >> 5;
    const int pair = (warp << 3) | (lane & 7);
    const int q    = lane >> 3;
    const int b0   = blockIdx.x * EPB;

    // ---- prefetch chunk 0 coefficients into registers ----
    float4 pf[3];
    float  pf_d21;
    {
        const float4* src = (const float4*)g_MT;   // 768 float4 per chunk
        pf[0] = src[tid];
        pf[1] = src[256 + tid];
        pf[2] = src[512 + tid];
        pf_d21 = g_D21T[tid];
    }

    // ---- load z = [x(64) | u(64)] into s_state (paired layout) ----
    {
        for (int idx = tid; idx < EPB * 64; idx += TB) {
            int e = idx >> 6, k = idx & 63;
            int pr = e >> 1, slot = e & 1;
            ((float*)(s_state + (size_t)k * SSTRIDE + pr))[slot]        = x0[b0 * 64 + idx];
            ((float*)(s_state + (size_t)(64 + k) * SSTRIDE + pr))[slot] = u[b0 * 64 + idx];
        }
    }

    ULL yacc[8];
#pragma unroll
    for (int m = 0; m < 8; m++) yacc[m] = 0ull;

    for (int c = 0; c < 32; c++) {
        __syncthreads();   // prior readers of staging buffers done
        // ---- stage chunk c from prefetch regs (duplicated for f32x2) ----
        {
            ulonglong2* dc = (ulonglong2*)s_coef;
#pragma unroll
            for (int i = 0; i < 3; i++) {
                int q4 = i * 256 + tid;
                dc[2 * q4]     = make_ulonglong2(pack2(pf[i].x, pf[i].x), pack2(pf[i].y, pf[i].y));
                dc[2 * q4 + 1] = make_ulonglong2(pack2(pf[i].z, pf[i].z), pack2(pf[i].w, pf[i].w));
            }
            s_d21[tid] = pack2(pf_d21, pf_d21);
            if (tid < 8) { float bv = g_bias[c * 8 + tid]; s_bias[tid] = pack2(bv, bv); }
            if (c < 16 && tid < 128) {
                int j = tid >> 5, m = tid & 31;
                float v = C2[m * 64 + c * 4 + j];
                s_c2[j * 32 + m] = pack2(v, v);
            }
        }
        // ---- prefetch chunk c+1 ----
        if (c < 31) {
            const float4* src = (const float4*)(g_MT + (c + 1) * 8 * NSTATE);
            pf[0] = src[tid];
            pf[1] = src[256 + tid];
            pf[2] = src[512 + tid];
            pf_d21 = g_D21T[(c + 1) * 256 + tid];
        }
        __syncthreads();   // staging visible

        // ---- partial GEMM: quarter q handles p = q, q+4, ... ----
        ULL acc[8];
#pragma unroll
        for (int k = 0; k < 8; k++) acc[k] = 0ull;
        const int P = 16 + c;
        for (int p = q; p < P; p += 4) {
            ULL sv[8];
#pragma unroll
            for (int j = 0; j < 8; j++) sv[j] = s_state[(size_t)(p * 8 + j) * SSTRIDE + pair];
#pragma unroll
            for (int k = 0; k < 8; k++) {
                const ulonglong2* cf = (const ulonglong2*)(s_coef + k * NSTATE + p * 8);
                ulonglong2 c0 = cf[0], c1 = cf[1], c2v = cf[2], c3 = cf[3];
                acc[k] = ffma2(sv[0], c0.x, acc[k]);
                acc[k] = ffma2(sv[1], c0.y, acc[k]);
                acc[k] = ffma2(sv[2], c1.x, acc[k]);
                acc[k] = ffma2(sv[3], c1.y, acc[k]);
                acc[k] = ffma2(sv[4], c2v.x, acc[k]);
                acc[k] = ffma2(sv[5], c2v.y, acc[k]);
                acc[k] = ffma2(sv[6], c3.x, acc[k]);
                acc[k] = ffma2(sv[7], c3.y, acc[k]);
            }
        }
        // ---- intra-warp reduction over q (lanes xor 8, 16) ----
#pragma unroll
        for (int k = 0; k < 8; k++) {
            acc[k] = fadd2(acc[k], shfl_xor64(acc[k], 8));
            acc[k] = fadd2(acc[k], shfl_xor64(acc[k], 16));
        }

        // ---- serial 8x8 diagonal + tanh (q==0 lanes only) ----
        if (q == 0) {
            ULL wl[8];
#pragma unroll
            for (int k = 0; k < 8; k++) {
                ULL a = fadd2(acc[k], s_bias[k]);
#pragma unroll
                for (int j = 0; j < 8; j++)
                    if (j < k) a = ffma2(wl[j], s_coef[k * NSTATE + 128 + c * 8 + j], a);
                float lo, hi; unpack2(a, lo, hi);
                wl[k] = pack2(tanhf(lo), tanhf(hi));
                s_state[(size_t)(128 + c * 8 + k) * SSTRIDE + pair] = wl[k];
            }
        }
        __syncwarp();

        // ---- y accumulation: quarter q owns m = 8q..8q+7 ----
        {
            ULL wv[8];
#pragma unroll
            for (int j = 0; j < 8; j++)
                wv[j] = s_state[(size_t)(128 + c * 8 + j) * SSTRIDE + pair];
#pragma unroll
            for (int j = 0; j < 8; j++)
#pragma unroll
                for (int mm = 0; mm < 8; mm++)
                    yacc[mm] = ffma2(wv[j], s_d21[j * 32 + q * 8 + mm], yacc[mm]);
        }
        if (c < 16) {
            ULL xv[4];
#pragma unroll
            for (int j = 0; j < 4; j++) xv[j] = s_state[(size_t)(c * 4 + j) * SSTRIDE + pair];
#pragma unroll
            for (int j = 0; j < 4; j++)
#pragma unroll
                for (int mm = 0; mm < 8; mm++)
                    yacc[mm] = ffma2(xv[j], s_c2[j * 32 + q * 8 + mm], yacc[mm]);
        }
    }

    // ---- output: stage to shared (reuse s_coef), then coalesced store ----
    __syncthreads();
    {
        float* s_out = (float*)s_coef;  // 128*33 floats = 4224 < 6144 avail
#pragma unroll
        for (int mm = 0; mm < 8; mm++) {
            int m = q * 8 + mm;
            float by = b[320 + m];
            float lo, hi; unpack2(yacc[mm], lo, hi);
            s_out[(2 * pair) * 33 + m]     = lo + by;
            s_out[(2 * pair + 1) * 33 + m] = hi + by;
        }
    }
    __syncthreads();
    {
        const float* s_out = (const float*)s_coef;
        for (int idx = tid; idx < EPB * 32; idx += TB) {
            int e = idx >> 5, m = idx & 31;
            out[(b0 + e) * 32 + m] = s_out[e * 33 + m];
        }
    }
}

// ---------------- launch ----------------

extern "C" void kernel_launch(void* const* d_in, const int* in_sizes, int n_in,
                              void* d_out, int out_size) {
    const float* u    = (const float*)d_in[0];
    const float* x0   = (const float*)d_in[1];
    const float* B2   = (const float*)d_in[2];
    const float* C2   = (const float*)d_in[3];
    const float* D12  = (const float*)d_in[4];
    const float* D21  = (const float*)d_in[5];
    const float* b    = (const float*)d_in[6];
    const float* X    = (const float*)d_in[7];
    // d_in[8] = Y1 (unused by reference)
    const float* St   = (const float*)d_in[9];
    const float* Q    = (const float*)d_in[10];
    const float* Rinv = (const float*)d_in[11];
    float* out = (float*)d_out;

    k_build_lT<<<NZ, 64>>>(B2, C2, D12, D21, St);
    k_build_M<<<NZ, 64>>>(Rinv, Q);
    k_build_H<<<(256 * 320) / 128, 128>>>(X);
    k_finalize<<<256, 128>>>(D12, D21, b);

    const size_t shbytes = (size_t)SM_TOTAL * sizeof(ULL);   // 227392 B
    cudaFuncSetAttribute(k_main, cudaFuncAttributeMaxDynamicSharedMemorySize, (int)shbytes);
    k_main<<<BATCH / EPB, TB, shbytes>>>(u, x0, C2, b, out);
}

// round 4
// speedup vs baseline: 1.7885x; 1.7885x over previous
#include <cuda_runtime.h>
#include <math.h>

#define NX 64
#define NUN 256
#define NY 32
#define NZ 384        // 2*NX + NUN
#define BATCH 32768
#define NSTATE 384    // 128 (z = x||u) + 256 (w)
#define EPB 128       // batch elements per block
#define PAIRS 64      // f32x2 pairs per block
#define TB 128        // threads per block (2 halves of 64 = 2 warps each)

typedef unsigned long long ULL;

// ---------------- f32x2 helpers (ptxas only emits FFMA2 from PTX) -------
__device__ __forceinline__ ULL ffma2(ULL a, ULL b, ULL c) {
    ULL d; asm("fma.rn.f32x2 %0, %1, %2, %3;" : "=l"(d) : "l"(a), "l"(b), "l"(c)); return d;
}
__device__ __forceinline__ ULL fadd2(ULL a, ULL b) {
    ULL d; asm("add.rn.f32x2 %0, %1, %2;" : "=l"(d) : "l"(a), "l"(b)); return d;
}
__device__ __forceinline__ ULL pack2(float lo, float hi) {
    ULL d; asm("mov.b64 %0, {%1,%2};" : "=l"(d) : "f"(lo), "f"(hi)); return d;
}
__device__ __forceinline__ void unpack2(ULL v, float& lo, float& hi) {
    asm("mov.b64 {%0,%1}, %2;" : "=f"(lo), "=f"(hi) : "l"(v));
}

// ---------------- device scratch (no cudaMalloc allowed) ----------------
__device__ __align__(16) float g_lT1[NZ * 64];
__device__ __align__(16) float g_lT2[NZ * 32];
__device__ __align__(16) float g_M1[NZ * 64];
__device__ __align__(16) float g_M2[NZ * 32];
__device__ __align__(16) float g_H[256 * 320];     // H[64+r][c], c in [0,320)
__device__ __align__(16) float g_MT[256 * NSTATE]; // row i: [C1*il | D12*il | Drows*il]
__device__ __align__(16) float g_bias[256];        // b_w[i] / lam[i]
__device__ __align__(16) float g_YW[320 * 32];     // rows 0..63: C2T, rows 64..319: D21T

// ---------------- setup kernels (batch-independent weights) --------------

__global__ void k_build_lT(const float* __restrict__ B2, const float* __restrict__ C2,
                           const float* __restrict__ D12, const float* __restrict__ D21,
                           const float* __restrict__ St) {
    int r = blockIdx.x;      // 0..383
    int k = threadIdx.x;     // 0..63
    float v1;
    if (r < 64) {
        float s = 0.f;
        for (int m = 0; m < 32; m++) s += St[k * 32 + m] * C2[m * 64 + r];
        v1 = s;
    } else if (r < 320) {
        int rr = r - 64;
        float s = 0.f;
        for (int m = 0; m < 32; m++) s += St[k * 32 + m] * D21[m * 256 + rr];
        v1 = s - D12[rr * 64 + k];
    } else {
        v1 = B2[(r - 320) * 64 + k];
    }
    g_lT1[r * 64 + k] = v1;
    if (k < 32) {
        float v2;
        if (r < 64)        v2 = C2[k * 64 + r];
        else if (r < 320)  v2 = D21[k * 256 + (r - 64)];
        else               v2 = 0.f;
        g_lT2[r * 32 + k] = v2;
    }
}

__global__ void k_build_M(const float* __restrict__ Rinv, const float* __restrict__ Q) {
    int r = blockIdx.x, k = threadIdx.x;
    float s = 0.f;
    for (int t = 0; t < 64; t++) s += g_lT1[r * 64 + t] * Rinv[t * 64 + k];
    g_M1[r * 64 + k] = s;
    if (k < 32) {
        float s2 = 0.f;
        for (int t = 0; t < 32; t++) s2 += g_lT2[r * 32 + t] * Q[t * 32 + k];
        g_M2[r * 32 + k] = s2;
    }
}

__global__ void k_build_H(const float* __restrict__ X) {
    int idx = blockIdx.x * blockDim.x + threadIdx.x;
    if (idx >= 256 * 320) return;
    int r = idx / 320, c = idx % 320;
    int a = 64 + r;
    float h = 0.f;
    for (int t = 0; t < NZ; t++) h += X[t * NZ + a] * X[t * NZ + c];
    if (c == a) h += 0.001f;
    float h1 = 0.f;
    for (int k = 0; k < 64; k++) h1 += g_M1[a * 64 + k] * g_lT1[c * 64 + k];
    float h2 = 0.f;
    for (int k = 0; k < 32; k++) h2 += g_M2[a * 32 + k] * g_lT2[c * 32 + k];
    g_H[idx] = h + h1 - h2;
}

// grid 320: rows 0..63 -> C2T into g_YW; rows 64..319 -> unit u: lam/bias/MT/D21T
__global__ void k_finalize(const float* __restrict__ D12, const float* __restrict__ D21,
                           const float* __restrict__ C2, const float* __restrict__ b) {
    int i = blockIdx.x;
    if (i < 64) {
        if (threadIdx.x < 32) g_YW[i * 32 + threadIdx.x] = C2[threadIdx.x * 64 + i];
        return;
    }
    int u = i - 64;  // 0..255
    __shared__ float s_inv;
    if (threadIdx.x == 0) {
        float lam = 0.5f * g_H[u * 320 + 64 + u];
        float inv = 1.f / lam;
        s_inv = inv;
        g_bias[u] = b[64 + u] * inv;
    }
    __syncthreads();
    float inv = s_inv;
    for (int t = threadIdx.x; t < NSTATE; t += blockDim.x) {
        float val;
        if (t < 64) {
            val = -g_H[u * 320 + t] * inv;
        } else if (t < 128) {
            val = D12[u * 64 + (t - 64)] * inv;
        } else {
            int j = t - 128;
            val = (u >= 1 && j <= u - 2) ? (-g_H[(u - 1) * 320 + 64 + j]) * inv : 0.f;
        }
        g_MT[u * NSTATE + t] = val;
    }
    if (threadIdx.x < 32) g_YW[i * 32 + threadIdx.x] = D21[threadIdx.x * 256 + u];
}

// ---------------- main kernel ---------------------------------------------
// 128 elems/block = 64 f32x2 pairs, 128 threads = 2 halves of 64 (2 warps each).
// Per chunk c (8 units):
//   [all]  p-loop partial dots over interleaved p-blocks (p%2 == half)
//   [h1]   write partials to s_red
//   bar
//   [h0]   combine + serial 8x8 diag + tanh + store w   (overlapped with:)
//   [h1]   stage chunk c+1 coef/diag/bias from prefetch regs, prefetch c+2
//   bar
// Tail: y = x@C2T + w@D21T in 5 rounds of 64 coef rows.
//
// Shared layout (ULL units):
#define SM_STATE 0                       // [384][64]        24576
#define SM_COEF  24576                   // [8][384] dup      3072 (tail: round coef / y staging)
#define SM_RED   (SM_COEF + 3072)        // [64][9]            576
#define SM_DIAG  (SM_RED + 576)          // [2][64] dup        128
#define SM_BIAS  (SM_DIAG + 128)         // [2][8] dup          16
#define SM_BY    (SM_BIAS + 16)          // 32 floats            4
#define SM_TOTAL (SM_BY + 4)             // 28372 ULL = 226976 B

__global__ void __launch_bounds__(TB, 1)
k_main(const float* __restrict__ u, const float* __restrict__ x0,
       const float* __restrict__ b, float* __restrict__ out) {
    extern __shared__ ULL sh[];
    ULL* s_state = sh + SM_STATE;
    ULL* s_coef  = sh + SM_COEF;
    ULL* s_red   = sh + SM_RED;
    ULL* s_diag  = sh + SM_DIAG;
    ULL* s_bias  = sh + SM_BIAS;
    float* s_by  = (float*)(sh + SM_BY);

    const int tid  = threadIdx.x;
    const int pair = tid & 63;
    const int half = tid >> 6;
    const int t2   = tid - 64;          // h1-local index (valid when half==1)
    const int b0   = blockIdx.x * EPB;

    // ---- h1: prefetch chunk 0 coefficients ----
    float2 pf2[24];
    float2 pf_diag;
    float  pf_b = 0.f;
    if (half) {
        const float2* src = (const float2*)g_MT;    // 1536 float2 per chunk
#pragma unroll
        for (int i = 0; i < 24; i++) pf2[i] = src[i * 64 + t2];
        if (t2 < 32) {
            int k = t2 >> 2, jj = t2 & 3;
            pf_diag = src[k * 192 + 64 + jj];        // chunk 0 diag block
        }
        if (t2 < 8) pf_b = g_bias[t2];
    }
    if (tid < 32) s_by[tid] = b[320 + tid];

    // ---- load z = [x(64) | u(64)] transposed, conflict-free ----
    {
        const float4* xs = (const float4*)(x0 + (size_t)(b0 + tid) * 64);
        const float4* us = (const float4*)(u  + (size_t)(b0 + tid) * 64);
        float* base = (float*)s_state + (tid >> 1) * 2 + (tid & 1);
#pragma unroll
        for (int q4 = 0; q4 < 16; q4++) {
            float4 xv = xs[q4], uv = us[q4];
            base[(q4 * 4 + 0) * 128] = xv.x;
            base[(q4 * 4 + 1) * 128] = xv.y;
            base[(q4 * 4 + 2) * 128] = xv.z;
            base[(q4 * 4 + 3) * 128] = xv.w;
            base[(64 + q4 * 4 + 0) * 128] = uv.x;
            base[(64 + q4 * 4 + 1) * 128] = uv.y;
            base[(64 + q4 * 4 + 2) * 128] = uv.z;
            base[(64 + q4 * 4 + 3) * 128] = uv.w;
        }
    }

    // ================= main chunk loop =================
    for (int c = 0; c < 32; c++) {
        if (half) {
            // ---- stage chunk c (conflict-free consecutive ulonglong2) ----
            ulonglong2* dc = (ulonglong2*)s_coef;
#pragma unroll
            for (int i = 0; i < 24; i++) {
                float2 v = pf2[i];
                dc[i * 64 + t2] = make_ulonglong2(pack2(v.x, v.x), pack2(v.y, v.y));
            }
            if (t2 < 32) {
                int k = t2 >> 2, jj = t2 & 3;
                float2 v = pf_diag;
                ((ulonglong2*)(s_diag + (c & 1) * 64))[k * 4 + jj] =
                    make_ulonglong2(pack2(v.x, v.x), pack2(v.y, v.y));
            }
            if (t2 < 8) s_bias[(c & 1) * 8 + t2] = pack2(pf_b, pf_b);
            // ---- prefetch chunk c+1 ----
            if (c < 31) {
                const float2* src = (const float2*)(g_MT + (c + 1) * 8 * NSTATE);
#pragma unroll
                for (int i = 0; i < 24; i++) pf2[i] = src[i * 64 + t2];
                if (t2 < 32) {
                    int k = t2 >> 2, jj = t2 & 3;
                    pf_diag = src[k * 192 + 64 + (c + 1) * 4 + jj];
                }
                if (t2 < 8) pf_b = g_bias[(c + 1) * 8 + t2];
            }
        } else if (c > 0) {
            // ---- diag of chunk c-1 (overlapped with h1 staging) ----
            int cp = c - 1;
            const ULL* dg = s_diag + (cp & 1) * 64;
            const ULL* bs = s_bias + (cp & 1) * 8;
            ULL wl[8];
#pragma unroll
            for (int k = 0; k < 8; k++) {
                ULL a = fadd2(sh[SM_RED + pair * 9 + k], bs[k]);
                // acc from previous chunk's p-loop is folded via s_red? no:
                // h0 partials stayed in regs — handled below (see accs carry).
                wl[k] = a;  // placeholder; real combine below
            }
            // NOTE: real diag executed after acc available — see post-p-loop diag.
            (void)wl; (void)dg;
        }
        __syncthreads();   // staging visible; w of chunk c-1 visible

        // ---- partial dots for chunk c ----
        ULL acc[8];
#pragma unroll
        for (int k = 0; k < 8; k++) acc[k] = 0ull;
        const int P = 16 + c;
#pragma unroll 2
        for (int p = half; p < P; p += 2) {
            ULL sv[8];
#pragma unroll
            for (int j = 0; j < 8; j++) sv[j] = s_state[(size_t)(p * 8 + j) * 64 + pair];
#pragma unroll
            for (int k = 0; k < 8; k++) {
                const ulonglong2* cf = (const ulonglong2*)(s_coef + k * NSTATE + p * 8);
                ulonglong2 c0 = cf[0], c1 = cf[1], c2v = cf[2], c3 = cf[3];
                acc[k] = ffma2(sv[0], c0.x, acc[k]);
                acc[k] = ffma2(sv[1], c0.y, acc[k]);
                acc[k] = ffma2(sv[2], c1.x, acc[k]);
                acc[k] = ffma2(sv[3], c1.y, acc[k]);
                acc[k] = ffma2(sv[4], c2v.x, acc[k]);
                acc[k] = ffma2(sv[5], c2v.y, acc[k]);
                acc[k] = ffma2(sv[6], c3.x, acc[k]);
                acc[k] = ffma2(sv[7], c3.y, acc[k]);
            }
        }
        if (half) {
#pragma unroll
            for (int k = 0; k < 8; k++) s_red[pair * 9 + k] = acc[k];
        }
        __syncthreads();   // partials visible

        if (!half) {
            // ---- combine + serial 8x8 diag + tanh + store w (chunk c) ----
            const ULL* dg = s_diag + (c & 1) * 64;
            const ULL* bs = s_bias + (c & 1) * 8;
            ULL wl[8];
#pragma unroll
            for (int k = 0; k < 8; k++) {
                ULL a = fadd2(acc[k], s_red[pair * 9 + k]);
                a = fadd2(a, bs[k]);
#pragma unroll
                for (int j = 0; j < 8; j++)
                    if (j < k) a = ffma2(wl[j], dg[k * 8 + j], a);
                float lo, hi; unpack2(a, lo, hi);
                wl[k] = pack2(tanhf(lo), tanhf(hi));
                s_state[(size_t)(128 + c * 8 + k) * 64 + pair] = wl[k];
            }
        }
        // next iteration's first barrier orders diag w-stores vs p-loop reads
    }

    // ================= tail: y = x@C2T + w@D21T =================
    ULL yacc[32];
#pragma unroll
    for (int m = 0; m < 32; m++) yacc[m] = 0ull;

    for (int r = 0; r < 5; r++) {
        __syncthreads();   // protect s_coef from previous readers (incl. diag31 path)
        {
            const float2* src = (const float2*)(g_YW + r * 64 * 32);
            ulonglong2* dst = (ulonglong2*)s_coef;
#pragma unroll
            for (int j = 0; j < 8; j++) {
                float2 v = src[j * 128 + tid];
                dst[j * 128 + tid] = make_ulonglong2(pack2(v.x, v.x), pack2(v.y, v.y));
            }
        }
        __syncthreads();
        const int srow = (r == 0) ? 0 : 128 + (r - 1) * 64;
        const int cbase = half * 32;
#pragma unroll 2
        for (int j = 0; j < 32; j++) {
            ULL sv = s_state[(size_t)(srow + cbase + j) * 64 + pair];
            const ulonglong2* cf = (const ulonglong2*)(s_coef + (size_t)(cbase + j) * 32);
#pragma unroll
            for (int mm = 0; mm < 16; mm++) {
                ulonglong2 cv = cf[mm];
                yacc[2 * mm]     = ffma2(sv, cv.x, yacc[2 * mm]);
                yacc[2 * mm + 1] = ffma2(sv, cv.y, yacc[2 * mm + 1]);
            }
        }
    }

    __syncthreads();
    if (half) {
#pragma unroll
        for (int m = 0; m < 32; m++) s_coef[pair * 33 + m] = yacc[m];
    }
    __syncthreads();
    if (!half) {
        float* s_outf = (float*)s_state;
#pragma unroll
        for (int m = 0; m < 32; m++) {
            ULL t = fadd2(yacc[m], s_coef[pair * 33 + m]);
            float lo, hi; unpack2(t, lo, hi);
            float by = s_by[m];
            s_outf[(2 * pair) * 33 + m]     = lo + by;
            s_outf[(2 * pair + 1) * 33 + m] = hi + by;
        }
    }
    __syncthreads();
    {
        const float* s_outf = (const float*)s_state;
        for (int idx = tid; idx < EPB * 32; idx += TB) {
            int e = idx >> 5, m = idx & 31;
            out[(b0 + e) * 32 + m] = s_outf[e * 33 + m];
        }
    }
}

// ---------------- launch ----------------

extern "C" void kernel_launch(void* const* d_in, const int* in_sizes, int n_in,
                              void* d_out, int out_size) {
    const float* u    = (const float*)d_in[0];
    const float* x0   = (const float*)d_in[1];
    const float* B2   = (const float*)d_in[2];
    const float* C2   = (const float*)d_in[3];
    const float* D12  = (const float*)d_in[4];
    const float* D21  = (const float*)d_in[5];
    const float* b    = (const float*)d_in[6];
    const float* X    = (const float*)d_in[7];
    // d_in[8] = Y1 (unused by reference)
    const float* St   = (const float*)d_in[9];
    const float* Q    = (const float*)d_in[10];
    const float* Rinv = (const float*)d_in[11];
    float* out = (float*)d_out;

    k_build_lT<<<NZ, 64>>>(B2, C2, D12, D21, St);
    k_build_M<<<NZ, 64>>>(Rinv, Q);
    k_build_H<<<(256 * 320) / 128, 128>>>(X);
    k_finalize<<<320, 128>>>(D12, D21, C2, b);

    const size_t shbytes = (size_t)SM_TOTAL * sizeof(ULL);   // 226976 B
    cudaFuncSetAttribute(k_main, cudaFuncAttributeMaxDynamicSharedMemorySize, (int)shbytes);
    k_main<<<BATCH / EPB, TB, shbytes>>>(u, x0, b, out);
}

// round 5
// speedup vs baseline: 1.7916x; 1.0017x over previous
#include <cuda_runtime.h>
#include <math.h>

#define NX 64
#define NUN 256
#define NY 32
#define NZ 384        // 2*NX + NUN
#define BATCH 32768
#define NSTATE 384    // 128 (z = x||u) + 256 (w)
#define EPB 128       // batch elements per block
#define PAIRS 64      // f32x2 pairs per block
#define TB 128        // threads per block (2 halves of 64 = 2 warps each)

typedef unsigned long long ULL;

// ---------------- f32x2 helpers (ptxas only emits FFMA2 from PTX) -------
__device__ __forceinline__ ULL ffma2(ULL a, ULL b, ULL c) {
    ULL d; asm("fma.rn.f32x2 %0, %1, %2, %3;" : "=l"(d) : "l"(a), "l"(b), "l"(c)); return d;
}
__device__ __forceinline__ ULL fadd2(ULL a, ULL b) {
    ULL d; asm("add.rn.f32x2 %0, %1, %2;" : "=l"(d) : "l"(a), "l"(b)); return d;
}
__device__ __forceinline__ ULL pack2(float lo, float hi) {
    ULL d; asm("mov.b64 %0, {%1,%2};" : "=l"(d) : "f"(lo), "f"(hi)); return d;
}
__device__ __forceinline__ void unpack2(ULL v, float& lo, float& hi) {
    asm("mov.b64 {%0,%1}, %2;" : "=f"(lo), "=f"(hi) : "l"(v));
}

// ---------------- device scratch (no cudaMalloc allowed) ----------------
__device__ __align__(16) float g_lT1[NZ * 64];
__device__ __align__(16) float g_lT2[NZ * 32];
__device__ __align__(16) float g_M1[NZ * 64];
__device__ __align__(16) float g_M2[NZ * 32];
__device__ __align__(16) float g_H[256 * 320];     // H[64+r][c], c in [0,320)
__device__ __align__(16) float g_MT[256 * NSTATE]; // row i: [C1*il | D12*il | Drows*il]
__device__ __align__(16) float g_bias[256];        // b_w[i] / lam[i]
__device__ __align__(16) float g_YW[320 * 32];     // rows 0..63: C2T, rows 64..319: D21T

// ---------------- setup kernels (batch-independent weights) --------------

__global__ void k_build_lT(const float* __restrict__ B2, const float* __restrict__ C2,
                           const float* __restrict__ D12, const float* __restrict__ D21,
                           const float* __restrict__ St) {
    int r = blockIdx.x;      // 0..383
    int k = threadIdx.x;     // 0..63
    float v1;
    if (r < 64) {
        float s = 0.f;
        for (int m = 0; m < 32; m++) s += St[k * 32 + m] * C2[m * 64 + r];
        v1 = s;
    } else if (r < 320) {
        int rr = r - 64;
        float s = 0.f;
        for (int m = 0; m < 32; m++) s += St[k * 32 + m] * D21[m * 256 + rr];
        v1 = s - D12[rr * 64 + k];
    } else {
        v1 = B2[(r - 320) * 64 + k];
    }
    g_lT1[r * 64 + k] = v1;
    if (k < 32) {
        float v2;
        if (r < 64)        v2 = C2[k * 64 + r];
        else if (r < 320)  v2 = D21[k * 256 + (r - 64)];
        else               v2 = 0.f;
        g_lT2[r * 32 + k] = v2;
    }
}

__global__ void k_build_M(const float* __restrict__ Rinv, const float* __restrict__ Q) {
    int r = blockIdx.x, k = threadIdx.x;
    float s = 0.f;
    for (int t = 0; t < 64; t++) s += g_lT1[r * 64 + t] * Rinv[t * 64 + k];
    g_M1[r * 64 + k] = s;
    if (k < 32) {
        float s2 = 0.f;
        for (int t = 0; t < 32; t++) s2 += g_lT2[r * 32 + t] * Q[t * 32 + k];
        g_M2[r * 32 + k] = s2;
    }
}

__global__ void k_build_H(const float* __restrict__ X) {
    int idx = blockIdx.x * blockDim.x + threadIdx.x;
    if (idx >= 256 * 320) return;
    int r = idx / 320, c = idx % 320;
    int a = 64 + r;
    float h = 0.f;
    for (int t = 0; t < NZ; t++) h += X[t * NZ + a] * X[t * NZ + c];
    if (c == a) h += 0.001f;
    float h1 = 0.f;
    for (int k = 0; k < 64; k++) h1 += g_M1[a * 64 + k] * g_lT1[c * 64 + k];
    float h2 = 0.f;
    for (int k = 0; k < 32; k++) h2 += g_M2[a * 32 + k] * g_lT2[c * 32 + k];
    g_H[idx] = h + h1 - h2;
}

// grid 320: rows 0..63 -> C2T into g_YW; rows 64..319 -> unit u: lam/bias/MT/D21T
__global__ void k_finalize(const float* __restrict__ D12, const float* __restrict__ D21,
                           const float* __restrict__ C2, const float* __restrict__ b) {
    int i = blockIdx.x;
    if (i < 64) {
        if (threadIdx.x < 32) g_YW[i * 32 + threadIdx.x] = C2[threadIdx.x * 64 + i];
        return;
    }
    int u = i - 64;  // 0..255
    __shared__ float s_inv;
    if (threadIdx.x == 0) {
        float lam = 0.5f * g_H[u * 320 + 64 + u];
        float inv = 1.f / lam;
        s_inv = inv;
        g_bias[u] = b[64 + u] * inv;
    }
    __syncthreads();
    float inv = s_inv;
    for (int t = threadIdx.x; t < NSTATE; t += blockDim.x) {
        float val;
        if (t < 64) {
            val = -g_H[u * 320 + t] * inv;
        } else if (t < 128) {
            val = D12[u * 64 + (t - 64)] * inv;
        } else {
            int j = t - 128;
            val = (u >= 1 && j <= u - 2) ? (-g_H[(u - 1) * 320 + 64 + j]) * inv : 0.f;
        }
        g_MT[u * NSTATE + t] = val;
    }
    if (threadIdx.x < 32) g_YW[i * 32 + threadIdx.x] = D21[threadIdx.x * 256 + u];
}

// ---------------- main kernel ---------------------------------------------
// 128 elems/block = 64 f32x2 pairs, 128 threads = 2 halves of 64 (2 warps each).
// Per chunk c (8 units):
//   [all]  p-loop partial dots over interleaved p-blocks (p%2 == half)
//   [h1]   write partials to s_red
//   bar
//   [h0]   combine + serial 8x8 diag + tanh + store w   (overlapped with:)
//   [h1]   stage chunk c+1 coef/diag/bias from prefetch regs, prefetch c+2
//   bar
// Tail: y = x@C2T + w@D21T in 5 rounds of 64 coef rows.
//
// Shared layout (ULL units):
#define SM_STATE 0                       // [384][64]        24576
#define SM_COEF  24576                   // [8][384] dup      3072 (tail: round coef / y staging)
#define SM_RED   (SM_COEF + 3072)        // [64][9]            576
#define SM_DIAG  (SM_RED + 576)          // [2][64] dup        128
#define SM_BIAS  (SM_DIAG + 128)         // [2][8] dup          16
#define SM_BY    (SM_BIAS + 16)          // 32 floats            4
#define SM_TOTAL (SM_BY + 4)             // 28372 ULL = 226976 B

__global__ void __launch_bounds__(TB, 1)
k_main(const float* __restrict__ u, const float* __restrict__ x0,
       const float* __restrict__ b, float* __restrict__ out) {
    extern __shared__ ULL sh[];
    ULL* s_state = sh + SM_STATE;
    ULL* s_coef  = sh + SM_COEF;
    ULL* s_red   = sh + SM_RED;
    ULL* s_diag  = sh + SM_DIAG;
    ULL* s_bias  = sh + SM_BIAS;
    float* s_by  = (float*)(sh + SM_BY);

    const int tid  = threadIdx.x;
    const int pair = tid & 63;
    const int half = tid >> 6;
    const int t2   = tid - 64;          // h1-local index (valid when half==1)
    const int b0   = blockIdx.x * EPB;

    // ---- h1: prefetch chunk 0 coefficients ----
    float2 pf2[24];
    float2 pf_diag;
    float  pf_b = 0.f;
    if (half) {
        const float2* src = (const float2*)g_MT;    // 1536 float2 per chunk
#pragma unroll
        for (int i = 0; i < 24; i++) pf2[i] = src[i * 64 + t2];
        if (t2 < 32) {
            int k = t2 >> 2, jj = t2 & 3;
            pf_diag = src[k * 192 + 64 + jj];        // chunk 0 diag block
        }
        if (t2 < 8) pf_b = g_bias[t2];
    }
    if (tid < 32) s_by[tid] = b[320 + tid];

    // ---- load z = [x(64) | u(64)] transposed, conflict-free ----
    {
        const float4* xs = (const float4*)(x0 + (size_t)(b0 + tid) * 64);
        const float4* us = (const float4*)(u  + (size_t)(b0 + tid) * 64);
        float* base = (float*)s_state + (tid >> 1) * 2 + (tid & 1);
#pragma unroll
        for (int q4 = 0; q4 < 16; q4++) {
            float4 xv = xs[q4], uv = us[q4];
            base[(q4 * 4 + 0) * 128] = xv.x;
            base[(q4 * 4 + 1) * 128] = xv.y;
            base[(q4 * 4 + 2) * 128] = xv.z;
            base[(q4 * 4 + 3) * 128] = xv.w;
            base[(64 + q4 * 4 + 0) * 128] = uv.x;
            base[(64 + q4 * 4 + 1) * 128] = uv.y;
            base[(64 + q4 * 4 + 2) * 128] = uv.z;
            base[(64 + q4 * 4 + 3) * 128] = uv.w;
        }
    }

    // ================= main chunk loop =================
    for (int c = 0; c < 32; c++) {
        if (half) {
            // ---- stage chunk c (conflict-free consecutive ulonglong2) ----
            ulonglong2* dc = (ulonglong2*)s_coef;
#pragma unroll
            for (int i = 0; i < 24; i++) {
                float2 v = pf2[i];
                dc[i * 64 + t2] = make_ulonglong2(pack2(v.x, v.x), pack2(v.y, v.y));
            }
            if (t2 < 32) {
                int k = t2 >> 2, jj = t2 & 3;
                float2 v = pf_diag;
                ((ulonglong2*)(s_diag + (c & 1) * 64))[k * 4 + jj] =
                    make_ulonglong2(pack2(v.x, v.x), pack2(v.y, v.y));
            }
            if (t2 < 8) s_bias[(c & 1) * 8 + t2] = pack2(pf_b, pf_b);
            // ---- prefetch chunk c+1 ----
            if (c < 31) {
                const float2* src = (const float2*)(g_MT + (c + 1) * 8 * NSTATE);
#pragma unroll
                for (int i = 0; i < 24; i++) pf2[i] = src[i * 64 + t2];
                if (t2 < 32) {
                    int k = t2 >> 2, jj = t2 & 3;
                    pf_diag = src[k * 192 + 64 + (c + 1) * 4 + jj];
                }
                if (t2 < 8) pf_b = g_bias[(c + 1) * 8 + t2];
            }
        } else if (c > 0) {
            // ---- diag of chunk c-1 (overlapped with h1 staging) ----
            int cp = c - 1;
            const ULL* dg = s_diag + (cp & 1) * 64;
            const ULL* bs = s_bias + (cp & 1) * 8;
            ULL wl[8];
#pragma unroll
            for (int k = 0; k < 8; k++) {
                ULL a = fadd2(sh[SM_RED + pair * 9 + k], bs[k]);
                // acc from previous chunk's p-loop is folded via s_red? no:
                // h0 partials stayed in regs — handled below (see accs carry).
                wl[k] = a;  // placeholder; real combine below
            }
            // NOTE: real diag executed after acc available — see post-p-loop diag.
            (void)wl; (void)dg;
        }
        __syncthreads();   // staging visible; w of chunk c-1 visible

        // ---- partial dots for chunk c ----
        ULL acc[8];
#pragma unroll
        for (int k = 0; k < 8; k++) acc[k] = 0ull;
        const int P = 16 + c;
#pragma unroll 2
        for (int p = half; p < P; p += 2) {
            ULL sv[8];
#pragma unroll
            for (int j = 0; j < 8; j++) sv[j] = s_state[(size_t)(p * 8 + j) * 64 + pair];
#pragma unroll
            for (int k = 0; k < 8; k++) {
                const ulonglong2* cf = (const ulonglong2*)(s_coef + k * NSTATE + p * 8);
                ulonglong2 c0 = cf[0], c1 = cf[1], c2v = cf[2], c3 = cf[3];
                acc[k] = ffma2(sv[0], c0.x, acc[k]);
                acc[k] = ffma2(sv[1], c0.y, acc[k]);
                acc[k] = ffma2(sv[2], c1.x, acc[k]);
                acc[k] = ffma2(sv[3], c1.y, acc[k]);
                acc[k] = ffma2(sv[4], c2v.x, acc[k]);
                acc[k] = ffma2(sv[5], c2v.y, acc[k]);
                acc[k] = ffma2(sv[6], c3.x, acc[k]);
                acc[k] = ffma2(sv[7], c3.y, acc[k]);
            }
        }
        if (half) {
#pragma unroll
            for (int k = 0; k < 8; k++) s_red[pair * 9 + k] = acc[k];
        }
        __syncthreads();   // partials visible

        if (!half) {
            // ---- combine + serial 8x8 diag + tanh + store w (chunk c) ----
            const ULL* dg = s_diag + (c & 1) * 64;
            const ULL* bs = s_bias + (c & 1) * 8;
            ULL wl[8];
#pragma unroll
            for (int k = 0; k < 8; k++) {
                ULL a = fadd2(acc[k], s_red[pair * 9 + k]);
                a = fadd2(a, bs[k]);
#pragma unroll
                for (int j = 0; j < 8; j++)
                    if (j < k) a = ffma2(wl[j], dg[k * 8 + j], a);
                float lo, hi; unpack2(a, lo, hi);
                wl[k] = pack2(tanhf(lo), tanhf(hi));
                s_state[(size_t)(128 + c * 8 + k) * 64 + pair] = wl[k];
            }
        }
        // next iteration's first barrier orders diag w-stores vs p-loop reads
    }

    // ================= tail: y = x@C2T + w@D21T =================
    ULL yacc[32];
#pragma unroll
    for (int m = 0; m < 32; m++) yacc[m] = 0ull;

    for (int r = 0; r < 5; r++) {
        __syncthreads();   // protect s_coef from previous readers (incl. diag31 path)
        {
            const float2* src = (const float2*)(g_YW + r * 64 * 32);
            ulonglong2* dst = (ulonglong2*)s_coef;
#pragma unroll
            for (int j = 0; j < 8; j++) {
                float2 v = src[j * 128 + tid];
                dst[j * 128 + tid] = make_ulonglong2(pack2(v.x, v.x), pack2(v.y, v.y));
            }
        }
        __syncthreads();
        const int srow = (r == 0) ? 0 : 128 + (r - 1) * 64;
        const int cbase = half * 32;
#pragma unroll 2
        for (int j = 0; j < 32; j++) {
            ULL sv = s_state[(size_t)(srow + cbase + j) * 64 + pair];
            const ulonglong2* cf = (const ulonglong2*)(s_coef + (size_t)(cbase + j) * 32);
#pragma unroll
            for (int mm = 0; mm < 16; mm++) {
                ulonglong2 cv = cf[mm];
                yacc[2 * mm]     = ffma2(sv, cv.x, yacc[2 * mm]);
                yacc[2 * mm + 1] = ffma2(sv, cv.y, yacc[2 * mm + 1]);
            }
        }
    }

    __syncthreads();
    if (half) {
#pragma unroll
        for (int m = 0; m < 32; m++) s_coef[pair * 33 + m] = yacc[m];
    }
    __syncthreads();
    if (!half) {
        float* s_outf = (float*)s_state;
#pragma unroll
        for (int m = 0; m < 32; m++) {
            ULL t = fadd2(yacc[m], s_coef[pair * 33 + m]);
            float lo, hi; unpack2(t, lo, hi);
            float by = s_by[m];
            s_outf[(2 * pair) * 33 + m]     = lo + by;
            s_outf[(2 * pair + 1) * 33 + m] = hi + by;
        }
    }
    __syncthreads();
    {
        const float* s_outf = (const float*)s_state;
        for (int idx = tid; idx < EPB * 32; idx += TB) {
            int e = idx >> 5, m = idx & 31;
            out[(b0 + e) * 32 + m] = s_outf[e * 33 + m];
        }
    }
}

// ---------------- launch ----------------

extern "C" void kernel_launch(void* const* d_in, const int* in_sizes, int n_in,
                              void* d_out, int out_size) {
    const float* u    = (const float*)d_in[0];
    const float* x0   = (const float*)d_in[1];
    const float* B2   = (const float*)d_in[2];
    const float* C2   = (const float*)d_in[3];
    const float* D12  = (const float*)d_in[4];
    const float* D21  = (const float*)d_in[5];
    const float* b    = (const float*)d_in[6];
    const float* X    = (const float*)d_in[7];
    // d_in[8] = Y1 (unused by reference)
    const float* St   = (const float*)d_in[9];
    const float* Q    = (const float*)d_in[10];
    const float* Rinv = (const float*)d_in[11];
    float* out = (float*)d_out;

    k_build_lT<<<NZ, 64>>>(B2, C2, D12, D21, St);
    k_build_M<<<NZ, 64>>>(Rinv, Q);
    k_build_H<<<(256 * 320) / 128, 128>>>(X);
    k_finalize<<<320, 128>>>(D12, D21, C2, b);

    const size_t shbytes = (size_t)SM_TOTAL * sizeof(ULL);   // 226976 B
    cudaFuncSetAttribute(k_main, cudaFuncAttributeMaxDynamicSharedMemorySize, (int)shbytes);
    k_main<<<BATCH / EPB, TB, shbytes>>>(u, x0, b, out);
}

// round 6
// speedup vs baseline: 1.9475x; 1.0870x over previous
#include <cuda_runtime.h>
#include <math.h>

#define NX 64
#define NUN 256
#define NY 32
#define NZ 384        // 2*NX + NUN
#define BATCH 32768
#define NSTATE 384    // 128 (z = x||u) + 256 (w)
#define EPB 64        // batch elements per block
#define TB 128        // threads per block: 2 halves of 64 (2 warps each)

typedef unsigned long long ULL;

// ---------------- f32x2 helpers (ptxas only emits FFMA2 from PTX) -------
__device__ __forceinline__ ULL ffma2(ULL a, ULL b, ULL c) {
    ULL d; asm("fma.rn.f32x2 %0, %1, %2, %3;" : "=l"(d) : "l"(a), "l"(b), "l"(c)); return d;
}
__device__ __forceinline__ ULL fadd2(ULL a, ULL b) {
    ULL d; asm("add.rn.f32x2 %0, %1, %2;" : "=l"(d) : "l"(a), "l"(b)); return d;
}
__device__ __forceinline__ ULL pack2(float lo, float hi) {
    ULL d; asm("mov.b64 %0, {%1,%2};" : "=l"(d) : "f"(lo), "f"(hi)); return d;
}
__device__ __forceinline__ void unpack2(ULL v, float& lo, float& hi) {
    asm("mov.b64 {%0,%1}, %2;" : "=f"(lo), "=f"(hi) : "l"(v));
}

// ---------------- device scratch (no cudaMalloc allowed) ----------------
__device__ __align__(16) float g_lT1[NZ * 64];
__device__ __align__(16) float g_lT2[NZ * 32];
__device__ __align__(16) float g_M1[NZ * 64];
__device__ __align__(16) float g_M2[NZ * 32];
__device__ __align__(16) float g_H[256 * 320];      // H[64+r][c], c in [0,320)
__device__ __align__(16) float g_bias[256];         // b_w[i] / lam[i]
// unit-pair packed coefs: chunk c, kp 0..3, t 0..383, slot = unit parity
// g_MTP[((c*4+kp)*384 + t)*2 + s] = MT[c*8+2*kp+s][t] (scaled by 1/lam)
__device__ __align__(16) float g_MTP[32 * 4 * 384 * 2];
// diag scalars: g_DG[c*64 + k*8 + j] = Drows-within-chunk (scaled), 0 if j>=k-ish
__device__ __align__(16) float g_DG[32 * 64];
// y-weights packed m-pairs: g_YWP[row*32 + m]; rows 0..63 = C2T, 64..319 = D21T
__device__ __align__(16) float g_YWP[320 * 32];

// ---------------- setup kernels (batch-independent weights) --------------

__global__ void k_build_lT(const float* __restrict__ B2, const float* __restrict__ C2,
                           const float* __restrict__ D12, const float* __restrict__ D21,
                           const float* __restrict__ St) {
    int r = blockIdx.x;      // 0..383
    int k = threadIdx.x;     // 0..63
    float v1;
    if (r < 64) {
        float s = 0.f;
        for (int m = 0; m < 32; m++) s += St[k * 32 + m] * C2[m * 64 + r];
        v1 = s;
    } else if (r < 320) {
        int rr = r - 64;
        float s = 0.f;
        for (int m = 0; m < 32; m++) s += St[k * 32 + m] * D21[m * 256 + rr];
        v1 = s - D12[rr * 64 + k];
    } else {
        v1 = B2[(r - 320) * 64 + k];
    }
    g_lT1[r * 64 + k] = v1;
    if (k < 32) {
        float v2;
        if (r < 64)        v2 = C2[k * 64 + r];
        else if (r < 320)  v2 = D21[k * 256 + (r - 64)];
        else               v2 = 0.f;
        g_lT2[r * 32 + k] = v2;
    }
}

__global__ void k_build_M(const float* __restrict__ Rinv, const float* __restrict__ Q) {
    int r = blockIdx.x, k = threadIdx.x;
    float s = 0.f;
    for (int t = 0; t < 64; t++) s += g_lT1[r * 64 + t] * Rinv[t * 64 + k];
    g_M1[r * 64 + k] = s;
    if (k < 32) {
        float s2 = 0.f;
        for (int t = 0; t < 32; t++) s2 += g_lT2[r * 32 + t] * Q[t * 32 + k];
        g_M2[r * 32 + k] = s2;
    }
}

__global__ void k_build_H(const float* __restrict__ X) {
    int idx = blockIdx.x * blockDim.x + threadIdx.x;
    if (idx >= 256 * 320) return;
    int r = idx / 320, c = idx % 320;
    int a = 64 + r;
    float h = 0.f;
    for (int t = 0; t < NZ; t++) h += X[t * NZ + a] * X[t * NZ + c];
    if (c == a) h += 0.001f;
    float h1 = 0.f;
    for (int k = 0; k < 64; k++) h1 += g_M1[a * 64 + k] * g_lT1[c * 64 + k];
    float h2 = 0.f;
    for (int k = 0; k < 32; k++) h2 += g_M2[a * 32 + k] * g_lT2[c * 32 + k];
    g_H[idx] = h + h1 - h2;
}

// grid 320: i<64 -> C2T rows of g_YWP; else unit uu: lam/bias/MTP/DG/D21T
__global__ void k_finalize(const float* __restrict__ D12, const float* __restrict__ D21,
                           const float* __restrict__ C2, const float* __restrict__ b) {
    int i = blockIdx.x;
    int tx = threadIdx.x;
    if (i < 64) {
        if (tx < 32) g_YWP[i * 32 + tx] = C2[tx * 64 + i];
        return;
    }
    int uu = i - 64;  // 0..255
    __shared__ float s_inv;
    if (tx == 0) {
        float lam = 0.5f * g_H[uu * 320 + 64 + uu];
        float inv = 1.f / lam;
        s_inv = inv;
        g_bias[uu] = b[64 + uu] * inv;
    }
    __syncthreads();
    float inv = s_inv;
    int c = uu >> 3, k = uu & 7;
    size_t base = (size_t)(c * 4 + (k >> 1)) * 768 + (k & 1);
    for (int t = tx; t < NSTATE; t += blockDim.x) {
        float val;
        if (t < 64) {
            val = -g_H[uu * 320 + t] * inv;                 // C_1 / lam
        } else if (t < 128) {
            val = D12[uu * 64 + (t - 64)] * inv;            // D_12 / lam
        } else {
            int j = t - 128;
            val = (uu >= 1 && j <= uu - 2) ? (-g_H[(uu - 1) * 320 + 64 + j]) * inv : 0.f;
        }
        g_MTP[base + (size_t)t * 2] = val;
    }
    if (tx < 8) {
        int j = c * 8 + tx;   // within-chunk column
        float val = (uu >= 1 && j <= uu - 2) ? (-g_H[(uu - 1) * 320 + 64 + j]) * inv : 0.f;
        g_DG[c * 64 + k * 8 + tx] = val;
    }
    if (tx < 32) g_YWP[(64 + uu) * 32 + tx] = D21[tx * 256 + uu];
}

// ---------------- main kernel ---------------------------------------------
// 64 elems/block, 128 threads = 2 halves of 64 (2 warps each). f32x2 packs
// UNIT pairs (2k, 2k+1); state is plain float in shared (no duplication) ->
// smem 113.9 KB -> 2 blocks/SM (2 warps/SMSP).
// Per chunk c:
//   [h1] stage chunk c coef/diag/bias (overlaps h0's diag of chunk c-1)
//   bar; [all] p-loop partial dots (p%2==half); [h1] partials -> s_red; bar
//   [h0] combine + serial 8x8 diag + tanh + store w
// Tail: y = x@C2T + w@D21T, 5 rounds of 64 rows, m-pair packed.
//
// Shared layout (ULL units):
#define SM_STATE 0                        // float[384][64]   = 12288 ULL
#define SM_COEF  12288                    // ULL[4][384]      =  1536 (reused in tail)
#define SM_RED   (SM_COEF + 1536)         // ULL[64][5]       =   320
#define SM_DIAG  (SM_RED + 320)           // float[2][64]     =    64
#define SM_BIAS  (SM_DIAG + 64)           // float[2][8]      =     8
#define SM_BY    (SM_BIAS + 8)            // float[32]        =    16
#define SM_TOTAL (SM_BY + 16)             // 14232 ULL = 113856 B

__global__ void __launch_bounds__(TB, 2)
k_main(const float* __restrict__ u, const float* __restrict__ x0,
       const float* __restrict__ b, float* __restrict__ out) {
    extern __shared__ ULL sh[];
    float* s_state = (float*)(sh + SM_STATE);
    ULL*   s_coef  = sh + SM_COEF;
    ULL*   s_red   = sh + SM_RED;
    float* s_diag  = (float*)(sh + SM_DIAG);
    float* s_bias  = (float*)(sh + SM_BIAS);
    float* s_by    = (float*)(sh + SM_BY);

    const int tid  = threadIdx.x;
    const int elem = tid & 63;
    const int half = tid >> 6;
    const int t2   = tid - 64;          // h1-local index
    const int b0   = blockIdx.x * EPB;

    // ---- h1: prefetch chunk 0 coefficients ----
    float4 pfc[12];
    float  pf_dg = 0.f, pf_b = 0.f;
    if (half) {
        const float4* src = (const float4*)g_MTP;   // 768 float4 per chunk
#pragma unroll
        for (int i = 0; i < 12; i++) pfc[i] = src[i * 64 + t2];
        pf_dg = g_DG[t2];
        if (t2 < 8) pf_b = g_bias[t2];
    }
    if (tid < 32) s_by[tid] = b[320 + tid];

    // ---- load z: threads 0-63 load x rows, 64-127 load u rows ----
    {
        const float4* src = (const float4*)((half ? u : x0) + (size_t)(b0 + elem) * 64);
        const int rbase = half * 64;
#pragma unroll
        for (int q4 = 0; q4 < 16; q4++) {
            float4 v = src[q4];
            s_state[(rbase + q4 * 4 + 0) * 64 + elem] = v.x;
            s_state[(rbase + q4 * 4 + 1) * 64 + elem] = v.y;
            s_state[(rbase + q4 * 4 + 2) * 64 + elem] = v.z;
            s_state[(rbase + q4 * 4 + 3) * 64 + elem] = v.w;
        }
    }

    // ================= main chunk loop =================
    for (int c = 0; c < 32; c++) {
        if (half) {
            // stage chunk c (float4 linear copy, conflict-free)
            float4* dst = (float4*)s_coef;
#pragma unroll
            for (int i = 0; i < 12; i++) dst[i * 64 + t2] = pfc[i];
            s_diag[(c & 1) * 64 + t2] = pf_dg;
            if (t2 < 8) s_bias[(c & 1) * 8 + t2] = pf_b;
            // prefetch chunk c+1
            if (c < 31) {
                const float4* src = (const float4*)(g_MTP + (size_t)(c + 1) * 3072);
#pragma unroll
                for (int i = 0; i < 12; i++) pfc[i] = src[i * 64 + t2];
                pf_dg = g_DG[(c + 1) * 64 + t2];
                if (t2 < 8) pf_b = g_bias[(c + 1) * 8 + t2];
            }
        }
        __syncthreads();   // staging + w(c-1) visible

        // ---- p-loop partial dots for chunk c ----
        ULL acc[4];
#pragma unroll
        for (int kp = 0; kp < 4; kp++) acc[kp] = 0ull;
        const int P = 16 + c;
#pragma unroll 2
        for (int p = half; p < P; p += 2) {
            ULL svd[8];
#pragma unroll
            for (int j = 0; j < 8; j++) {
                float v = s_state[(p * 8 + j) * 64 + elem];
                svd[j] = pack2(v, v);
            }
#pragma unroll
            for (int kp = 0; kp < 4; kp++) {
                const ulonglong2* cf = (const ulonglong2*)(s_coef + kp * NSTATE + p * 8);
                ulonglong2 c0 = cf[0], c1 = cf[1], c2v = cf[2], c3 = cf[3];
                acc[kp] = ffma2(svd[0], c0.x, acc[kp]);
                acc[kp] = ffma2(svd[1], c0.y, acc[kp]);
                acc[kp] = ffma2(svd[2], c1.x, acc[kp]);
                acc[kp] = ffma2(svd[3], c1.y, acc[kp]);
                acc[kp] = ffma2(svd[4], c2v.x, acc[kp]);
                acc[kp] = ffma2(svd[5], c2v.y, acc[kp]);
                acc[kp] = ffma2(svd[6], c3.x, acc[kp]);
                acc[kp] = ffma2(svd[7], c3.y, acc[kp]);
            }
        }
        if (half) {
#pragma unroll
            for (int kp = 0; kp < 4; kp++) s_red[elem * 5 + kp] = acc[kp];
        }
        __syncthreads();   // partials visible

        if (!half) {
            // ---- combine + serial 8x8 diag + tanh + store w ----
            float a[8];
#pragma unroll
            for (int kp = 0; kp < 4; kp++) {
                ULL t = fadd2(acc[kp], s_red[elem * 5 + kp]);
                unpack2(t, a[2 * kp], a[2 * kp + 1]);
            }
            const float* dg = s_diag + (c & 1) * 64;
            const float* bs = s_bias + (c & 1) * 8;
            float wl[8];
#pragma unroll
            for (int k = 0; k < 8; k++) {
                float s = a[k] + bs[k];
#pragma unroll
                for (int j = 0; j < 8; j++)
                    if (j < k) s += wl[j] * dg[k * 8 + j];
                wl[k] = tanhf(s);
                s_state[(128 + c * 8 + k) * 64 + elem] = wl[k];
            }
        }
        // next iteration's first barrier orders diag w-stores vs p-loop reads
    }

    // ================= tail: y = x@C2T + w@D21T =================
    ULL yacc[16];
#pragma unroll
    for (int q = 0; q < 16; q++) yacc[q] = 0ull;

    for (int r = 0; r < 5; r++) {
        __syncthreads();   // protect s_coef from previous readers
        {
            const float4* src = (const float4*)g_YWP + r * 512;  // 64 rows x 32 floats
            float4* dst = (float4*)s_coef;
#pragma unroll
            for (int i = 0; i < 4; i++) dst[i * 128 + tid] = src[i * 128 + tid];
        }
        __syncthreads();
        const int srow = (r == 0) ? 0 : 128 + (r - 1) * 64;
#pragma unroll 2
        for (int jj = 0; jj < 32; jj++) {
            int lrow = half * 32 + jj;
            float v = s_state[(srow + lrow) * 64 + elem];
            ULL vd = pack2(v, v);
            const ulonglong2* cf = (const ulonglong2*)(s_coef + lrow * 16);
#pragma unroll
            for (int mm = 0; mm < 8; mm++) {
                ulonglong2 cv = cf[mm];
                yacc[2 * mm]     = ffma2(vd, cv.x, yacc[2 * mm]);
                yacc[2 * mm + 1] = ffma2(vd, cv.y, yacc[2 * mm + 1]);
            }
        }
    }

    __syncthreads();
    if (half) {
#pragma unroll
        for (int q = 0; q < 16; q++) s_coef[elem * 17 + q] = yacc[q];
    }
    __syncthreads();
    if (!half) {
        float* s_out = s_state;   // reuse state as output staging
#pragma unroll
        for (int q = 0; q < 16; q++) {
            ULL t = fadd2(yacc[q], s_coef[elem * 17 + q]);
            float lo, hi; unpack2(t, lo, hi);
            s_out[elem * 33 + 2 * q]     = lo + s_by[2 * q];
            s_out[elem * 33 + 2 * q + 1] = hi + s_by[2 * q + 1];
        }
    }
    __syncthreads();
    {
        const float* s_out = s_state;
        for (int idx = tid; idx < EPB * 32; idx += TB) {
            int e = idx >> 5, m = idx & 31;
            out[(b0 + e) * 32 + m] = s_out[e * 33 + m];
        }
    }
}

// ---------------- launch ----------------

extern "C" void kernel_launch(void* const* d_in, const int* in_sizes, int n_in,
                              void* d_out, int out_size) {
    const float* u    = (const float*)d_in[0];
    const float* x0   = (const float*)d_in[1];
    const float* B2   = (const float*)d_in[2];
    const float* C2   = (const float*)d_in[3];
    const float* D12  = (const float*)d_in[4];
    const float* D21  = (const float*)d_in[5];
    const float* b    = (const float*)d_in[6];
    const float* X    = (const float*)d_in[7];
    // d_in[8] = Y1 (unused by reference)
    const float* St   = (const float*)d_in[9];
    const float* Q    = (const float*)d_in[10];
    const float* Rinv = (const float*)d_in[11];
    float* out = (float*)d_out;

    k_build_lT<<<NZ, 64>>>(B2, C2, D12, D21, St);
    k_build_M<<<NZ, 64>>>(Rinv, Q);
    k_build_H<<<(256 * 320) / 128, 128>>>(X);
    k_finalize<<<320, 128>>>(D12, D21, C2, b);

    const size_t shbytes = (size_t)SM_TOTAL * sizeof(ULL);   // 113856 B
    cudaFuncSetAttribute(k_main, cudaFuncAttributeMaxDynamicSharedMemorySize, (int)shbytes);
    k_main<<<BATCH / EPB, TB, shbytes>>>(u, x0, b, out);
}